// round 1
// baseline (speedup 1.0000x reference)
#include <cuda_runtime.h>
#include <cstdint>

#define N_RES   20000
#define N_EDGE  640000
#define NUM_RBF 16
#define NUM_AA  21
#define FEAT    340
#define EPSV    1e-8f
#define EPB     8          // edges per block

// ---------------- device scratch (no mallocs allowed) ----------------
__device__ float g_bb[N_RES * 12];      // n, ca, c, cb  (xyz each)
__device__ float g_R[N_RES * 9];        // row-major R[i*3+j]
__device__ float g_t[N_RES * 3];
__device__ float g_local[N_RES * 12];   // R^T (bb - t)
__device__ float g_noised[N_RES];
__device__ int   g_mask_kind;           // 0=bool(u8), 1=int32, 2=float32

__constant__ float c_freq[8] = {
    1.0f, 0.31622776601683794f, 0.1f, 0.03162277660168379f,
    0.01f, 0.0031622776601683794f, 0.001f, 0.00031622776601683794f
};

// ---------------- mask dtype detection ----------------
// Reads the first 5000 32-bit words (= 20000 bytes, safe under every
// interpretation). int32 0/1 mask -> all words in {0,1}. float32 0/1 mask ->
// all words in {0, 0x3F800000}. Packed bool bytes -> neither (50% bernoulli
// over 20000 samples makes ambiguity probability ~0).
__global__ void detect_mask_kind_kernel(const unsigned int* __restrict__ m) {
    __shared__ int not01, notf;
    if (threadIdx.x == 0) { not01 = 0; notf = 0; }
    __syncthreads();
    for (int i = threadIdx.x; i < 5000; i += blockDim.x) {
        unsigned int v = m[i];
        if (v > 1u) not01 = 1;                    // benign race
        if (v != 0u && v != 0x3F800000u) notf = 1;
    }
    __syncthreads();
    if (threadIdx.x == 0) {
        int kind;
        if (!notf)       kind = 2;   // float32
        else if (!not01) kind = 1;   // int32
        else             kind = 0;   // bool bytes
        g_mask_kind = kind;
    }
}

// ---------------- per-residue precompute ----------------
__global__ void residue_kernel(const float* __restrict__ atom14,
                               const float* __restrict__ rig,
                               const void*  __restrict__ mask) {
    int r = blockIdx.x * blockDim.x + threadIdx.x;
    if (r >= N_RES) return;

    const float* a = atom14 + (size_t)r * 42;   // 14 atoms * 3
    float n0 = a[0], n1 = a[1], n2 = a[2];
    float ca0 = a[3], ca1 = a[4], ca2 = a[5];
    float c0 = a[6], c1 = a[7], c2 = a[8];

    float b0 = ca0 - n0, b1 = ca1 - n1, b2 = ca2 - n2;
    float e0 = c0 - ca0, e1 = c1 - ca1, e2 = c2 - ca2;
    float ax = b1 * e2 - b2 * e1;
    float ay = b2 * e0 - b0 * e2;
    float az = b0 * e1 - b1 * e0;
    float cb0 = -0.58273431f * ax + 0.56802827f * b0 - 0.54067466f * e0 + ca0;
    float cb1 = -0.58273431f * ay + 0.56802827f * b1 - 0.54067466f * e1 + ca1;
    float cb2 = -0.58273431f * az + 0.56802827f * b2 - 0.54067466f * e2 + ca2;

    float bb[12] = { n0, n1, n2, ca0, ca1, ca2, c0, c1, c2, cb0, cb1, cb2 };
    #pragma unroll
    for (int i = 0; i < 12; i++) g_bb[r * 12 + i] = bb[i];

    const float* q = rig + (size_t)r * 7;
    float qw = q[0], qx = q[1], qy = q[2], qz = q[3];
    float inv = rsqrtf(qw * qw + qx * qx + qy * qy + qz * qz);
    qw *= inv; qx *= inv; qy *= inv; qz *= inv;

    float R[9];
    R[0] = 1.f - 2.f * (qy * qy + qz * qz);
    R[1] = 2.f * (qx * qy - qw * qz);
    R[2] = 2.f * (qx * qz + qw * qy);
    R[3] = 2.f * (qx * qy + qw * qz);
    R[4] = 1.f - 2.f * (qx * qx + qz * qz);
    R[5] = 2.f * (qy * qz - qw * qx);
    R[6] = 2.f * (qx * qz - qw * qy);
    R[7] = 2.f * (qy * qz + qw * qx);
    R[8] = 1.f - 2.f * (qx * qx + qy * qy);
    #pragma unroll
    for (int i = 0; i < 9; i++) g_R[r * 9 + i] = R[i];

    float t0 = q[4], t1 = q[5], t2 = q[6];
    g_t[r * 3 + 0] = t0; g_t[r * 3 + 1] = t1; g_t[r * 3 + 2] = t2;

    // local[k][i] = sum_j R[j][i] * (bb[k][j] - t[j])
    #pragma unroll
    for (int k = 0; k < 4; k++) {
        float vx = bb[k * 3 + 0] - t0;
        float vy = bb[k * 3 + 1] - t1;
        float vz = bb[k * 3 + 2] - t2;
        #pragma unroll
        for (int i = 0; i < 3; i++) {
            g_local[r * 12 + k * 3 + i] = R[0 + i] * vx + R[3 + i] * vy + R[6 + i] * vz;
        }
    }

    int kind = g_mask_kind;
    float noised;
    if (kind == 0)      noised = ((const unsigned char*)mask)[r] ? 1.f : 0.f;
    else if (kind == 1) noised = ((const int*)mask)[r] ? 1.f : 0.f;
    else                noised = (((const float*)mask)[r] != 0.f) ? 1.f : 0.f;
    g_noised[r] = noised;
}

// ---------------- per-edge feature kernel: 1 warp / edge ----------------
__global__ __launch_bounds__(EPB * 32) void edge_kernel(
    const int* __restrict__ eidx,     // [2, N_EDGE]: row0=dst, row1=src
    const int* __restrict__ seq,
    float* __restrict__ out) {

    __shared__ __align__(16) float sfeat[EPB][FEAT];
    __shared__ float sstage[EPB][48];

    int w    = threadIdx.x >> 5;
    int lane = threadIdx.x & 31;
    int e    = blockIdx.x * EPB + w;

    int dst = eidx[e];
    int src = eidx[N_EDGE + e];

    float* st = sstage[w];
    // stage: [0..11] bb_src, [12..23] bb_dst, [24..32] R_src, [33..35] t_src,
    //        [36..47] local_src
    #pragma unroll
    for (int rr = 0; rr < 2; rr++) {
        int idx = lane + rr * 32;
        if (idx < 48) {
            float v;
            if (idx < 12)      v = g_bb[src * 12 + idx];
            else if (idx < 24) v = g_bb[dst * 12 + (idx - 12)];
            else if (idx < 33) v = g_R[src * 9 + (idx - 24)];
            else if (idx < 36) v = g_t[src * 3 + (idx - 33)];
            else               v = g_local[src * 12 + (idx - 36)];
            st[idx] = v;
        }
    }
    float noised_src = g_noised[src];
    float noised_dst = g_noised[dst];
    float keep_src = 1.f - noised_src;
    float keep_dst = 1.f - noised_dst;
    int seq_src = seq[src];
    int seq_dst = seq[dst];
    __syncwarp();

    float* f = sfeat[w];

    // ---- region A: [0..43] flags + one-hots ----
    #pragma unroll
    for (int rr = 0; rr < 2; rr++) {
        int idx = lane + rr * 32;
        if (idx < 44) {
            float v;
            if (idx == 0)      v = noised_dst;
            else if (idx == 1) v = noised_src;
            else if (idx < 23) v = (seq_src == idx - 2)  ? keep_src : 0.f;
            else               v = (seq_dst == idx - 23) ? keep_dst : 0.f;
            f[idx] = v;
        }
    }

    // ---- region B: [44..299] RBF(dists 4x4, 16 bins) ----
    {
        int p = lane >> 1;          // pair 0..15
        int h = lane & 1;           // bin half
        int i = p >> 2;             // src atom
        int j = p & 3;              // dst atom
        float dx = st[i * 3 + 0] - st[12 + j * 3 + 0] + EPSV;
        float dy = st[i * 3 + 1] - st[12 + j * 3 + 1] + EPSV;
        float dz = st[i * 3 + 2] - st[12 + j * 3 + 2] + EPSV;
        float D = sqrtf(dx * dx + dy * dy + dz * dz);
        #pragma unroll
        for (int mm = 0; mm < 8; mm++) {
            int m = h * 8 + mm;
            float mu = 2.0f + (float)m * (20.0f / 15.0f);
            float z = (D - mu) * 0.8f;           // / sigma, sigma = 1.25
            f[44 + p * 16 + m] = __expf(-z * z);
        }
    }

    // ---- region C: [300..315] positional enc (accurate sin/cos: args big) ----
    if (lane < 16) {
        float dp = (float)(dst - src);
        int k = lane & 7;
        float ang = dp * c_freq[k];
        f[300 + lane] = (lane < 8) ? cosf(ang) : sinf(ang);
    }

    // ---- regions D,E: [316..327] src local frame, [328..339] dst in src frame ----
    if (lane < 12) {
        f[316 + lane] = st[36 + lane] * keep_src;
        int kk = lane / 3, ii = lane - kk * 3;
        float v = 0.f;
        #pragma unroll
        for (int jj = 0; jj < 3; jj++)
            v += st[24 + jj * 3 + ii] * (st[12 + kk * 3 + jj] - st[33 + jj]);
        f[328 + lane] = v * keep_dst;
    }

    __syncthreads();

    // ---- coalesced block-wide store: 8 edges * 340 f32 = 680 float4 ----
    const float4* s4 = (const float4*)&sfeat[0][0];
    float4* o4 = (float4*)(out + (size_t)blockIdx.x * (EPB * FEAT));
    for (int idx = threadIdx.x; idx < (EPB * FEAT) / 4; idx += blockDim.x)
        o4[idx] = s4[idx];
}

// ---------------- launch ----------------
extern "C" void kernel_launch(void* const* d_in, const int* in_sizes, int n_in,
                              void* d_out, int out_size) {
    const float* atom14 = (const float*)d_in[0];
    const float* rigids = (const float*)d_in[1];
    const int*   seq    = (const int*)d_in[2];
    const void*  mask   = d_in[3];
    const int*   eidx   = (const int*)d_in[4];
    float* out = (float*)d_out;

    detect_mask_kind_kernel<<<1, 256>>>((const unsigned int*)mask);
    residue_kernel<<<(N_RES + 255) / 256, 256>>>(atom14, rigids, mask);
    edge_kernel<<<N_EDGE / EPB, EPB * 32>>>(eidx, seq, out);
}

// round 2
// speedup vs baseline: 1.0496x; 1.0496x over previous
#include <cuda_runtime.h>
#include <cstdint>

#define N_RES   20000
#define N_EDGE  640000
#define NUM_AA  21
#define FEAT    340
#define EPSV    1e-8f
#define EPB     8          // edges (warps) per block

// ---------------- device scratch (no mallocs allowed) ----------------
__device__ float g_bb[N_RES * 12];      // n, ca, c, cb  (xyz each)
__device__ float g_R[N_RES * 9];        // row-major R[i*3+j]
__device__ float g_t[N_RES * 3];
__device__ float g_local[N_RES * 12];   // R^T (bb - t)
__device__ float g_noised[N_RES];
__device__ int   g_mask_kind;           // 0=bool(u8), 1=int32, 2=float32

__constant__ float c_freq[8] = {
    1.0f, 0.31622776601683794f, 0.1f, 0.03162277660168379f,
    0.01f, 0.0031622776601683794f, 0.001f, 0.00031622776601683794f
};

// ---------------- mask dtype detection ----------------
// Reads the first 5000 32-bit words (= 20000 bytes, in-bounds under every
// interpretation). int32 0/1 -> words all in {0,1}. float32 0/1 -> words all
// in {0, 0x3F800000}. Packed bool bytes -> neither (prob of ambiguity ~0).
__global__ void detect_mask_kind_kernel(const unsigned int* __restrict__ m) {
    __shared__ int not01, notf;
    if (threadIdx.x == 0) { not01 = 0; notf = 0; }
    __syncthreads();
    for (int i = threadIdx.x; i < 5000; i += blockDim.x) {
        unsigned int v = m[i];
        if (v > 1u) not01 = 1;                    // benign race
        if (v != 0u && v != 0x3F800000u) notf = 1;
    }
    __syncthreads();
    if (threadIdx.x == 0) {
        int kind;
        if (!notf)       kind = 2;   // float32
        else if (!not01) kind = 1;   // int32
        else             kind = 0;   // bool bytes
        g_mask_kind = kind;
    }
}

// ---------------- per-residue precompute ----------------
__global__ void residue_kernel(const float* __restrict__ atom14,
                               const float* __restrict__ rig,
                               const void*  __restrict__ mask) {
    int r = blockIdx.x * blockDim.x + threadIdx.x;
    if (r >= N_RES) return;

    const float* a = atom14 + (size_t)r * 42;   // 14 atoms * 3
    float n0 = a[0], n1 = a[1], n2 = a[2];
    float ca0 = a[3], ca1 = a[4], ca2 = a[5];
    float c0 = a[6], c1 = a[7], c2 = a[8];

    float b0 = ca0 - n0, b1 = ca1 - n1, b2 = ca2 - n2;
    float e0 = c0 - ca0, e1 = c1 - ca1, e2 = c2 - ca2;
    float ax = b1 * e2 - b2 * e1;
    float ay = b2 * e0 - b0 * e2;
    float az = b0 * e1 - b1 * e0;
    float cb0 = -0.58273431f * ax + 0.56802827f * b0 - 0.54067466f * e0 + ca0;
    float cb1 = -0.58273431f * ay + 0.56802827f * b1 - 0.54067466f * e1 + ca1;
    float cb2 = -0.58273431f * az + 0.56802827f * b2 - 0.54067466f * e2 + ca2;

    float bb[12] = { n0, n1, n2, ca0, ca1, ca2, c0, c1, c2, cb0, cb1, cb2 };
    #pragma unroll
    for (int i = 0; i < 12; i++) g_bb[r * 12 + i] = bb[i];

    const float* q = rig + (size_t)r * 7;
    float qw = q[0], qx = q[1], qy = q[2], qz = q[3];
    float inv = rsqrtf(qw * qw + qx * qx + qy * qy + qz * qz);
    qw *= inv; qx *= inv; qy *= inv; qz *= inv;

    float R[9];
    R[0] = 1.f - 2.f * (qy * qy + qz * qz);
    R[1] = 2.f * (qx * qy - qw * qz);
    R[2] = 2.f * (qx * qz + qw * qy);
    R[3] = 2.f * (qx * qy + qw * qz);
    R[4] = 1.f - 2.f * (qx * qx + qz * qz);
    R[5] = 2.f * (qy * qz - qw * qx);
    R[6] = 2.f * (qx * qz - qw * qy);
    R[7] = 2.f * (qy * qz + qw * qx);
    R[8] = 1.f - 2.f * (qx * qx + qy * qy);
    #pragma unroll
    for (int i = 0; i < 9; i++) g_R[r * 9 + i] = R[i];

    float t0 = q[4], t1 = q[5], t2 = q[6];
    g_t[r * 3 + 0] = t0; g_t[r * 3 + 1] = t1; g_t[r * 3 + 2] = t2;

    // local[k][i] = sum_j R[j][i] * (bb[k][j] - t[j])
    #pragma unroll
    for (int k = 0; k < 4; k++) {
        float vx = bb[k * 3 + 0] - t0;
        float vy = bb[k * 3 + 1] - t1;
        float vz = bb[k * 3 + 2] - t2;
        #pragma unroll
        for (int i = 0; i < 3; i++) {
            g_local[r * 12 + k * 3 + i] = R[0 + i] * vx + R[3 + i] * vy + R[6 + i] * vz;
        }
    }

    int kind = g_mask_kind;
    float noised;
    if (kind == 0)      noised = ((const unsigned char*)mask)[r] ? 1.f : 0.f;
    else if (kind == 1) noised = ((const int*)mask)[r] ? 1.f : 0.f;
    else                noised = (((const float*)mask)[r] != 0.f) ? 1.f : 0.f;
    g_noised[r] = noised;
}

// ---------------- per-edge feature kernel: 1 warp / edge ----------------
__global__ __launch_bounds__(EPB * 32) void edge_kernel(
    const int* __restrict__ eidx,     // [2, N_EDGE]: row0=dst, row1=src
    const int* __restrict__ seq,
    float* __restrict__ out) {

    __shared__ __align__(16) float sfeat[EPB][FEAT];
    __shared__ float sstage[EPB][48];

    int w    = threadIdx.x >> 5;
    int lane = threadIdx.x & 31;
    int e    = blockIdx.x * EPB + w;

    int dst = eidx[e];
    int src = eidx[N_EDGE + e];

    float* st = sstage[w];
    // stage: [0..11] bb_src, [12..23] bb_dst, [24..32] R_src, [33..35] t_src,
    //        [36..47] local_src
    {
        int idx = lane;
        float v;
        if (idx < 12)      v = g_bb[src * 12 + idx];
        else if (idx < 24) v = g_bb[dst * 12 + (idx - 12)];
        else               v = g_R[src * 9 + (idx - 24)];  // idx 24..31 -> R[0..7]
        st[idx] = v;
        idx = lane + 32;
        if (idx < 48) {
            if (idx == 32)      v = g_R[src * 9 + 8];
            else if (idx < 36)  v = g_t[src * 3 + (idx - 33)];
            else                v = g_local[src * 12 + (idx - 36)];
            st[idx] = v;
        }
    }
    float noised_src = g_noised[src];
    float noised_dst = g_noised[dst];
    float keep_src = 1.f - noised_src;
    float keep_dst = 1.f - noised_dst;
    int seq_src = seq[src];
    int seq_dst = seq[dst];
    __syncwarp();

    float* f = sfeat[w];

    // ---- region A: [0..43] flags + one-hots, 11 lanes x STS.128 ----
    if (lane < 11) {
        float4 v;
        float* vp = &v.x;
        #pragma unroll
        for (int cc = 0; cc < 4; cc++) {
            int idx = 4 * lane + cc;
            float x;
            if (idx == 0)       x = noised_dst;
            else if (idx == 1)  x = noised_src;
            else if (idx < 23)  x = (idx - 2  == seq_src) ? keep_src : 0.f;
            else                x = (idx - 23 == seq_dst) ? keep_dst : 0.f;
            vp[cc] = x;
        }
        *(float4*)&f[4 * lane] = v;
    }

    // ---- region B: [44..299] RBF of 16 dists, 16 bins each ----
    // lanes 0..15 each compute one distance; broadcast via shuffle;
    // each lane then owns (pair = lane>>1, half = lane&1) -> 8 bins -> 2 STS.128
    float D;
    {
        int p = lane & 15;          // pair for lanes 0..15 (junk for 16..31)
        int i = p >> 2;             // src atom
        int j = p & 3;              // dst atom
        float dx = st[i * 3 + 0] - st[12 + j * 3 + 0] + EPSV;
        float dy = st[i * 3 + 1] - st[12 + j * 3 + 1] + EPSV;
        float dz = st[i * 3 + 2] - st[12 + j * 3 + 2] + EPSV;
        D = sqrtf(dx * dx + dy * dy + dz * dz);
    }
    D = __shfl_sync(0xFFFFFFFFu, D, lane >> 1);
    {
        int p = lane >> 1;          // pair 0..15
        int h = lane & 1;           // bin half
        float r[8];
        #pragma unroll
        for (int mm = 0; mm < 8; mm++) {
            int m = h * 8 + mm;     // h is uniform per-lane at compile? no; both halves unrolled below
            float mu = 2.0f + (float)m * (20.0f / 15.0f);
            float z = (D - mu) * 0.8f;           // / sigma, sigma = 1.25
            r[mm] = __expf(-z * z);
        }
        float* base = &f[44 + p * 16 + h * 8];
        *(float4*)base       = make_float4(r[0], r[1], r[2], r[3]);
        *(float4*)(base + 4) = make_float4(r[4], r[5], r[6], r[7]);
    }

    // ---- region C: [300..315] positional enc (fast sin/cos, HW range red.) ----
    if (lane < 16) {
        float dp = (float)(dst - src);
        float ang = dp * c_freq[lane & 7];
        f[300 + lane] = (lane < 8) ? __cosf(ang) : __sinf(ang);
    }

    // ---- regions D,E: [316..327] src local frame, [328..339] dst in src frame ----
    if (lane < 12) {
        f[316 + lane] = st[36 + lane] * keep_src;
        int kk = lane / 3, ii = lane - kk * 3;
        float v = 0.f;
        #pragma unroll
        for (int jj = 0; jj < 3; jj++)
            v += st[24 + jj * 3 + ii] * (st[12 + kk * 3 + jj] - st[33 + jj]);
        f[328 + lane] = v * keep_dst;
    }

    __syncwarp();

    // ---- per-warp coalesced store: 340 floats = 85 float4 ----
    const float4* s4 = (const float4*)f;
    float4* o4 = (float4*)(out + (size_t)e * FEAT);
    o4[lane]      = s4[lane];
    o4[lane + 32] = s4[lane + 32];
    if (lane < 21) o4[lane + 64] = s4[lane + 64];
}

// ---------------- launch ----------------
extern "C" void kernel_launch(void* const* d_in, const int* in_sizes, int n_in,
                              void* d_out, int out_size) {
    const float* atom14 = (const float*)d_in[0];
    const float* rigids = (const float*)d_in[1];
    const int*   seq    = (const int*)d_in[2];
    const void*  mask   = d_in[3];
    const int*   eidx   = (const int*)d_in[4];
    float* out = (float*)d_out;

    detect_mask_kind_kernel<<<1, 256>>>((const unsigned int*)mask);
    residue_kernel<<<(N_RES + 255) / 256, 256>>>(atom14, rigids, mask);
    edge_kernel<<<N_EDGE / EPB, EPB * 32>>>(eidx, seq, out);
}

// round 3
// speedup vs baseline: 1.1454x; 1.0913x over previous
#include <cuda_runtime.h>
#include <cstdint>

#define N_RES   20000
#define N_EDGE  640000
#define NUM_AA  21
#define FEAT    340
#define EPSV    1e-8f
#define EPB     8          // edges (warps) per block

// ---------------- device scratch (no mallocs allowed) ----------------
__device__ float g_bb[N_RES * 12];      // n, ca, c, cb  (xyz each)
__device__ float g_R[N_RES * 9];        // row-major R[i*3+j]
__device__ float g_t[N_RES * 3];
__device__ float g_local[N_RES * 12];   // R^T (bb - t)
__device__ int   g_mask_kind;           // 0=bool(u8), 1=int32, 2=float32

__constant__ float c_freq[8] = {
    1.0f, 0.31622776601683794f, 0.1f, 0.03162277660168379f,
    0.01f, 0.0031622776601683794f, 0.001f, 0.00031622776601683794f
};

// ---------------- prep: residue geometry + mask dtype detection ----------------
// Grid = 80 blocks x 256. Blocks 0..78 cover the 20000 residues; block 79 does
// mask-dtype detection with batched (MLP=19) loads.
// Detection: reads first 4864 32-bit words (= 19456 bytes, in-bounds under every
// interpretation of the 20000-element mask). int32 0/1 -> words all in {0,1};
// float32 0/1 -> words all in {0, 0x3F800000}; packed bool bytes -> neither.
__global__ void prep_kernel(const float* __restrict__ atom14,
                            const float* __restrict__ rig,
                            const unsigned int* __restrict__ mask_w) {
    if (blockIdx.x == 79) {
        __shared__ int s_not01, s_notf;
        if (threadIdx.x == 0) { s_not01 = 0; s_notf = 0; }
        __syncthreads();
        unsigned int v[19];
        #pragma unroll
        for (int k = 0; k < 19; k++) v[k] = mask_w[threadIdx.x + 256 * k];
        int not01 = 0, notf = 0;
        #pragma unroll
        for (int k = 0; k < 19; k++) {
            if (v[k] > 1u) not01 = 1;
            if (v[k] != 0u && v[k] != 0x3F800000u) notf = 1;
        }
        if (not01) atomicOr(&s_not01, 1);
        if (notf)  atomicOr(&s_notf, 1);
        __syncthreads();
        if (threadIdx.x == 0) {
            int kind;
            if (!s_notf)       kind = 2;   // float32
            else if (!s_not01) kind = 1;   // int32
            else               kind = 0;   // bool bytes
            g_mask_kind = kind;
        }
        return;
    }

    int r = blockIdx.x * blockDim.x + threadIdx.x;
    if (r >= N_RES) return;

    const float* a = atom14 + (size_t)r * 42;   // 14 atoms * 3
    float n0 = a[0], n1 = a[1], n2 = a[2];
    float ca0 = a[3], ca1 = a[4], ca2 = a[5];
    float c0 = a[6], c1 = a[7], c2 = a[8];

    float b0 = ca0 - n0, b1 = ca1 - n1, b2 = ca2 - n2;
    float e0 = c0 - ca0, e1 = c1 - ca1, e2 = c2 - ca2;
    float ax = b1 * e2 - b2 * e1;
    float ay = b2 * e0 - b0 * e2;
    float az = b0 * e1 - b1 * e0;
    float cb0 = -0.58273431f * ax + 0.56802827f * b0 - 0.54067466f * e0 + ca0;
    float cb1 = -0.58273431f * ay + 0.56802827f * b1 - 0.54067466f * e1 + ca1;
    float cb2 = -0.58273431f * az + 0.56802827f * b2 - 0.54067466f * e2 + ca2;

    float bb[12] = { n0, n1, n2, ca0, ca1, ca2, c0, c1, c2, cb0, cb1, cb2 };
    #pragma unroll
    for (int i = 0; i < 12; i++) g_bb[r * 12 + i] = bb[i];

    const float* q = rig + (size_t)r * 7;
    float qw = q[0], qx = q[1], qy = q[2], qz = q[3];
    float inv = rsqrtf(qw * qw + qx * qx + qy * qy + qz * qz);
    qw *= inv; qx *= inv; qy *= inv; qz *= inv;

    float R[9];
    R[0] = 1.f - 2.f * (qy * qy + qz * qz);
    R[1] = 2.f * (qx * qy - qw * qz);
    R[2] = 2.f * (qx * qz + qw * qy);
    R[3] = 2.f * (qx * qy + qw * qz);
    R[4] = 1.f - 2.f * (qx * qx + qz * qz);
    R[5] = 2.f * (qy * qz - qw * qx);
    R[6] = 2.f * (qx * qz - qw * qy);
    R[7] = 2.f * (qy * qz + qw * qx);
    R[8] = 1.f - 2.f * (qx * qx + qy * qy);
    #pragma unroll
    for (int i = 0; i < 9; i++) g_R[r * 9 + i] = R[i];

    float t0 = q[4], t1 = q[5], t2 = q[6];
    g_t[r * 3 + 0] = t0; g_t[r * 3 + 1] = t1; g_t[r * 3 + 2] = t2;

    // local[k][i] = sum_j R[j][i] * (bb[k][j] - t[j])
    #pragma unroll
    for (int k = 0; k < 4; k++) {
        float vx = bb[k * 3 + 0] - t0;
        float vy = bb[k * 3 + 1] - t1;
        float vz = bb[k * 3 + 2] - t2;
        #pragma unroll
        for (int i = 0; i < 3; i++) {
            g_local[r * 12 + k * 3 + i] = R[0 + i] * vx + R[3 + i] * vy + R[6 + i] * vz;
        }
    }
}

// ---------------- per-edge feature kernel: 1 warp / edge, direct-to-GMEM ----------------
__global__ __launch_bounds__(EPB * 32) void edge_kernel(
    const int* __restrict__ eidx,     // [2, N_EDGE]: row0=dst, row1=src
    const int* __restrict__ seq,
    const void* __restrict__ mask,
    float* __restrict__ out) {

    __shared__ float sstage[EPB][36];

    int w    = threadIdx.x >> 5;
    int lane = threadIdx.x & 31;
    int e    = blockIdx.x * EPB + w;

    int dst = eidx[e];
    int src = eidx[N_EDGE + e];

    float* st = sstage[w];
    // stage: [0..11] bb_src, [12..23] bb_dst, [24..32] R_src, [33..35] t_src
    {
        float v;
        if (lane < 12)      v = g_bb[src * 12 + lane];
        else if (lane < 24) v = g_bb[dst * 12 + (lane - 12)];
        else                v = g_R[src * 9 + (lane - 24)];  // lanes 24..31 -> R[0..7]
        st[lane] = v;
        if (lane < 4) {
            st[32 + lane] = (lane == 0) ? g_R[src * 9 + 8] : g_t[src * 3 + (lane - 1)];
        }
    }

    int kind = g_mask_kind;                         // grid-uniform branch
    float noised_src, noised_dst;
    if (kind == 0) {
        noised_src = ((const unsigned char*)mask)[src] ? 1.f : 0.f;
        noised_dst = ((const unsigned char*)mask)[dst] ? 1.f : 0.f;
    } else if (kind == 1) {
        noised_src = ((const int*)mask)[src] ? 1.f : 0.f;
        noised_dst = ((const int*)mask)[dst] ? 1.f : 0.f;
    } else {
        noised_src = (((const float*)mask)[src] != 0.f) ? 1.f : 0.f;
        noised_dst = (((const float*)mask)[dst] != 0.f) ? 1.f : 0.f;
    }
    float keep_src = 1.f - noised_src;
    float keep_dst = 1.f - noised_dst;
    int hot_src = seq[src] + 2;    // position of src one-hot within row
    int hot_dst = seq[dst] + 23;   // position of dst one-hot within row
    __syncwarp();

    float* __restrict__ row = out + (size_t)e * FEAT;

    // ---- region A: [0..43] flags + one-hots, 11 lanes x STG.128 ----
    if (lane < 11) {
        float4 v4;
        float* vp = &v4.x;
        #pragma unroll
        for (int cc = 0; cc < 4; cc++) {
            int idx = 4 * lane + cc;
            float x = (idx == hot_src) ? keep_src : ((idx == hot_dst) ? keep_dst : 0.f);
            if (idx == 0) x = noised_dst;
            if (idx == 1) x = noised_src;
            vp[cc] = x;
        }
        *(float4*)(row + 4 * lane) = v4;
    }

    // ---- region B: [44..299] RBF of 16 dists, 16 bins each ----
    // lanes 0..15 compute the 16 distances; broadcast via shuffle; each lane
    // owns (pair = lane>>1, half = lane&1) -> 8 bins -> 2 STG.128 (contiguous 1KB)
    float D;
    {
        int p = lane & 15;
        int i = p >> 2;             // src atom
        int j = p & 3;              // dst atom
        float dx = st[i * 3 + 0] - st[12 + j * 3 + 0] + EPSV;
        float dy = st[i * 3 + 1] - st[12 + j * 3 + 1] + EPSV;
        float dz = st[i * 3 + 2] - st[12 + j * 3 + 2] + EPSV;
        D = sqrtf(dx * dx + dy * dy + dz * dz);
    }
    D = __shfl_sync(0xFFFFFFFFu, D, lane >> 1);
    {
        int p = lane >> 1;          // pair 0..15
        int h = lane & 1;           // bin half
        float mu0 = 2.0f + (float)(h * 8) * (20.0f / 15.0f);
        float r[8];
        #pragma unroll
        for (int mm = 0; mm < 8; mm++) {
            float mu = mu0 + (float)mm * (20.0f / 15.0f);
            float z = (D - mu) * 0.8f;           // / sigma, sigma = 1.25
            r[mm] = __expf(-z * z);
        }
        float* base = row + 44 + p * 16 + h * 8;
        *(float4*)base       = make_float4(r[0], r[1], r[2], r[3]);
        *(float4*)(base + 4) = make_float4(r[4], r[5], r[6], r[7]);
    }

    // ---- region C: [300..315] positional enc (fast sin/cos, HW range red.) ----
    if (lane < 16) {
        float dp = (float)(dst - src);
        float ang = dp * c_freq[lane & 7];
        row[300 + lane] = (lane < 8) ? __cosf(ang) : __sinf(ang);
    }

    // ---- region D: [316..327] src local frame (direct L2 gather) ----
    if (lane < 12) {
        row[316 + lane] = g_local[src * 12 + lane] * keep_src;
    }

    // ---- region E: [328..339] dst backbone in src frame ----
    if (lane < 12) {
        int kk = lane / 3, ii = lane - kk * 3;
        float v = 0.f;
        #pragma unroll
        for (int jj = 0; jj < 3; jj++)
            v += st[24 + jj * 3 + ii] * (st[12 + kk * 3 + jj] - st[33 + jj]);
        row[328 + lane] = v * keep_dst;
    }
}

// ---------------- launch ----------------
extern "C" void kernel_launch(void* const* d_in, const int* in_sizes, int n_in,
                              void* d_out, int out_size) {
    const float* atom14 = (const float*)d_in[0];
    const float* rigids = (const float*)d_in[1];
    const int*   seq    = (const int*)d_in[2];
    const void*  mask   = d_in[3];
    const int*   eidx   = (const int*)d_in[4];
    float* out = (float*)d_out;

    prep_kernel<<<80, 256>>>(atom14, rigids, (const unsigned int*)mask);
    edge_kernel<<<N_EDGE / EPB, EPB * 32>>>(eidx, seq, mask, out);
}

// round 4
// speedup vs baseline: 1.3443x; 1.1736x over previous
#include <cuda_runtime.h>
#include <cstdint>

#define N_RES   20000
#define N_EDGE  640000
#define NUM_AA  21
#define FEAT    340
#define EPSV    1e-8f
#define EPB     8          // edges (warps) per block

// ---------------- device scratch (no mallocs allowed) ----------------
__device__ float g_bb[N_RES * 12];      // n, ca, c, cb  (xyz each)
__device__ float g_R[N_RES * 9];        // row-major R[i*3+j]
__device__ float g_t[N_RES * 3];
__device__ float g_local[N_RES * 12];   // R^T (bb - t)
__device__ int   g_mask_kind;           // 0=bool(u8), 1=int32, 2=float32

__constant__ float c_freq[8] = {
    1.0f, 0.31622776601683794f, 0.1f, 0.03162277660168379f,
    0.01f, 0.0031622776601683794f, 0.001f, 0.00031622776601683794f
};

// ---------------- prep: residue geometry + mask dtype detection ----------------
// Grid = 80 blocks x 256. Blocks 0..78 cover the 20000 residues; block 79 does
// mask-dtype detection with batched (MLP=19) loads.
// Detection: reads first 4864 32-bit words (= 19456 bytes, in-bounds under every
// interpretation of the 20000-element mask). int32 0/1 -> words all in {0,1};
// float32 0/1 -> words all in {0, 0x3F800000}; packed bool bytes -> neither.
__global__ void prep_kernel(const float* __restrict__ atom14,
                            const float* __restrict__ rig,
                            const unsigned int* __restrict__ mask_w) {
    if (blockIdx.x == 79) {
        __shared__ int s_not01, s_notf;
        if (threadIdx.x == 0) { s_not01 = 0; s_notf = 0; }
        __syncthreads();
        unsigned int v[19];
        #pragma unroll
        for (int k = 0; k < 19; k++) v[k] = mask_w[threadIdx.x + 256 * k];
        int not01 = 0, notf = 0;
        #pragma unroll
        for (int k = 0; k < 19; k++) {
            if (v[k] > 1u) not01 = 1;
            if (v[k] != 0u && v[k] != 0x3F800000u) notf = 1;
        }
        if (not01) atomicOr(&s_not01, 1);
        if (notf)  atomicOr(&s_notf, 1);
        __syncthreads();
        if (threadIdx.x == 0) {
            int kind;
            if (!s_notf)       kind = 2;   // float32
            else if (!s_not01) kind = 1;   // int32
            else               kind = 0;   // bool bytes
            g_mask_kind = kind;
        }
        return;
    }

    int r = blockIdx.x * blockDim.x + threadIdx.x;
    if (r >= N_RES) return;

    const float* a = atom14 + (size_t)r * 42;   // 14 atoms * 3
    float n0 = a[0], n1 = a[1], n2 = a[2];
    float ca0 = a[3], ca1 = a[4], ca2 = a[5];
    float c0 = a[6], c1 = a[7], c2 = a[8];

    float b0 = ca0 - n0, b1 = ca1 - n1, b2 = ca2 - n2;
    float e0 = c0 - ca0, e1 = c1 - ca1, e2 = c2 - ca2;
    float ax = b1 * e2 - b2 * e1;
    float ay = b2 * e0 - b0 * e2;
    float az = b0 * e1 - b1 * e0;
    float cb0 = -0.58273431f * ax + 0.56802827f * b0 - 0.54067466f * e0 + ca0;
    float cb1 = -0.58273431f * ay + 0.56802827f * b1 - 0.54067466f * e1 + ca1;
    float cb2 = -0.58273431f * az + 0.56802827f * b2 - 0.54067466f * e2 + ca2;

    float bb[12] = { n0, n1, n2, ca0, ca1, ca2, c0, c1, c2, cb0, cb1, cb2 };
    #pragma unroll
    for (int i = 0; i < 12; i++) g_bb[r * 12 + i] = bb[i];

    const float* q = rig + (size_t)r * 7;
    float qw = q[0], qx = q[1], qy = q[2], qz = q[3];
    float inv = rsqrtf(qw * qw + qx * qx + qy * qy + qz * qz);
    qw *= inv; qx *= inv; qy *= inv; qz *= inv;

    float R[9];
    R[0] = 1.f - 2.f * (qy * qy + qz * qz);
    R[1] = 2.f * (qx * qy - qw * qz);
    R[2] = 2.f * (qx * qz + qw * qy);
    R[3] = 2.f * (qx * qy + qw * qz);
    R[4] = 1.f - 2.f * (qx * qx + qz * qz);
    R[5] = 2.f * (qy * qz - qw * qx);
    R[6] = 2.f * (qx * qz - qw * qy);
    R[7] = 2.f * (qy * qz + qw * qx);
    R[8] = 1.f - 2.f * (qx * qx + qy * qy);
    #pragma unroll
    for (int i = 0; i < 9; i++) g_R[r * 9 + i] = R[i];

    float t0 = q[4], t1 = q[5], t2 = q[6];
    g_t[r * 3 + 0] = t0; g_t[r * 3 + 1] = t1; g_t[r * 3 + 2] = t2;

    // local[k][i] = sum_j R[j][i] * (bb[k][j] - t[j])
    #pragma unroll
    for (int k = 0; k < 4; k++) {
        float vx = bb[k * 3 + 0] - t0;
        float vy = bb[k * 3 + 1] - t1;
        float vz = bb[k * 3 + 2] - t2;
        #pragma unroll
        for (int i = 0; i < 3; i++) {
            g_local[r * 12 + k * 3 + i] = R[0 + i] * vx + R[3 + i] * vy + R[6 + i] * vz;
        }
    }
}

// ---------------- per-edge feature kernel: 1 warp / edge, direct-to-GMEM ----------------
__global__ __launch_bounds__(EPB * 32) void edge_kernel(
    const int* __restrict__ eidx,     // [2, N_EDGE]: row0=dst, row1=src
    const int* __restrict__ seq,
    const void* __restrict__ mask,
    float* __restrict__ out) {

    __shared__ float sstage[EPB][36];

    int w    = threadIdx.x >> 5;
    int lane = threadIdx.x & 31;
    int e    = blockIdx.x * EPB + w;

    int dst = eidx[e];
    int src = eidx[N_EDGE + e];

    float* st = sstage[w];
    // stage: [0..11] bb_src, [12..23] bb_dst, [24..32] R_src, [33..35] t_src
    {
        float v;
        if (lane < 12)      v = g_bb[src * 12 + lane];
        else if (lane < 24) v = g_bb[dst * 12 + (lane - 12)];
        else                v = g_R[src * 9 + (lane - 24)];  // lanes 24..31 -> R[0..7]
        st[lane] = v;
        if (lane < 4) {
            st[32 + lane] = (lane == 0) ? g_R[src * 9 + 8] : g_t[src * 3 + (lane - 1)];
        }
    }

    int kind = g_mask_kind;                         // grid-uniform branch
    float noised_src, noised_dst;
    if (kind == 0) {
        noised_src = ((const unsigned char*)mask)[src] ? 1.f : 0.f;
        noised_dst = ((const unsigned char*)mask)[dst] ? 1.f : 0.f;
    } else if (kind == 1) {
        noised_src = ((const int*)mask)[src] ? 1.f : 0.f;
        noised_dst = ((const int*)mask)[dst] ? 1.f : 0.f;
    } else {
        noised_src = (((const float*)mask)[src] != 0.f) ? 1.f : 0.f;
        noised_dst = (((const float*)mask)[dst] != 0.f) ? 1.f : 0.f;
    }
    float keep_src = 1.f - noised_src;
    float keep_dst = 1.f - noised_dst;
    int hot_src = seq[src] + 2;    // one-hot position within row, in [2,22]
    int hot_dst = seq[dst] + 23;   // one-hot position within row, in [23,43]
    __syncwarp();

    float* __restrict__ row = out + (size_t)e * FEAT;

    // ---- region A: [0..43] flags + one-hots, 11 lanes x STG.128 ----
    if (lane < 11) {
        float4 v4;
        float* vp = &v4.x;
        #pragma unroll
        for (int cc = 0; cc < 4; cc++) {
            int idx = 4 * lane + cc;
            float x = (idx == hot_src) ? keep_src : 0.f;
            x = (idx == hot_dst) ? keep_dst : x;
            vp[cc] = x;
        }
        if (lane == 0) { v4.x = noised_dst; v4.y = noised_src; }
        __stcs((float4*)(row + 4 * lane), v4);
    }

    // ---- region B: [44..299] RBF of 16 dists, 16 bins each ----
    // lanes 0..15 compute the 16 distances; two dense STG.128 sweeps cover
    // floats [44..171] and [172..299] contiguously (4 wavefronts each).
    float D;
    {
        int p = lane & 15;
        int i = p >> 2;             // src atom
        int j = p & 3;              // dst atom
        float dx = st[i * 3 + 0] - st[12 + j * 3 + 0] + EPSV;
        float dy = st[i * 3 + 1] - st[12 + j * 3 + 1] + EPSV;
        float dz = st[i * 3 + 2] - st[12 + j * 3 + 2] + EPSV;
        D = sqrtf(dx * dx + dy * dy + dz * dz);
    }
    {
        // sweep 1: lane L -> floats [44+4L..47+4L], pair = L>>2, bins 4*(L&3)..+3
        float Da = __shfl_sync(0xFFFFFFFFu, D, lane >> 2);
        float mu0 = 2.0f + (float)(4 * (lane & 3)) * (20.0f / 15.0f);
        float r0, r1, r2, r3, z;
        z = (Da - mu0) * 0.8f;                         r0 = __expf(-z * z);
        z = (Da - (mu0 + 1.3333333333333333f)) * 0.8f; r1 = __expf(-z * z);
        z = (Da - (mu0 + 2.6666666666666665f)) * 0.8f; r2 = __expf(-z * z);
        z = (Da - (mu0 + 4.0f)) * 0.8f;                r3 = __expf(-z * z);
        __stcs((float4*)(row + 44 + 4 * lane), make_float4(r0, r1, r2, r3));

        // sweep 2: lane L -> floats [172+4L..175+4L], pair = 8 + (L>>2)
        float Db = __shfl_sync(0xFFFFFFFFu, D, 8 + (lane >> 2));
        z = (Db - mu0) * 0.8f;                         r0 = __expf(-z * z);
        z = (Db - (mu0 + 1.3333333333333333f)) * 0.8f; r1 = __expf(-z * z);
        z = (Db - (mu0 + 2.6666666666666665f)) * 0.8f; r2 = __expf(-z * z);
        z = (Db - (mu0 + 4.0f)) * 0.8f;                r3 = __expf(-z * z);
        __stcs((float4*)(row + 172 + 4 * lane), make_float4(r0, r1, r2, r3));
    }

    // ---- region C: [300..315] positional enc (fast sin/cos, HW range red.) ----
    if (lane < 16) {
        float dp = (float)(dst - src);
        float ang = dp * c_freq[lane & 7];
        __stcs(row + 300 + lane, (lane < 8) ? __cosf(ang) : __sinf(ang));
    }

    // ---- regions D+E fused: [316..339] one predicated STG over 24 lanes ----
    // lanes 0..11:  src local frame (direct L2 gather) * keep_src
    // lanes 12..23: dst backbone in src frame * keep_dst
    if (lane < 24) {
        float v;
        if (lane < 12) {
            v = g_local[src * 12 + lane] * keep_src;
        } else {
            int l = lane - 12;
            int kk = l / 3, ii = l - kk * 3;
            float acc = 0.f;
            #pragma unroll
            for (int jj = 0; jj < 3; jj++)
                acc += st[24 + jj * 3 + ii] * (st[12 + kk * 3 + jj] - st[33 + jj]);
            v = acc * keep_dst;
        }
        __stcs(row + 316 + lane, v);
    }
}

// ---------------- launch ----------------
extern "C" void kernel_launch(void* const* d_in, const int* in_sizes, int n_in,
                              void* d_out, int out_size) {
    const float* atom14 = (const float*)d_in[0];
    const float* rigids = (const float*)d_in[1];
    const int*   seq    = (const int*)d_in[2];
    const void*  mask   = d_in[3];
    const int*   eidx   = (const int*)d_in[4];
    float* out = (float*)d_out;

    prep_kernel<<<80, 256>>>(atom14, rigids, (const unsigned int*)mask);
    edge_kernel<<<N_EDGE / EPB, EPB * 32>>>(eidx, seq, mask, out);
}

// round 5
// speedup vs baseline: 1.6193x; 1.2046x over previous
#include <cuda_runtime.h>
#include <cstdint>

#define N_RES   20000
#define N_EDGE  640000
#define NUM_AA  21
#define FEAT    340
#define EPSV    1e-8f
#define EPB     8          // edges (warps) per block

// ---------------- device scratch (no mallocs allowed) ----------------
__device__ float4 g_bb4[N_RES * 4];     // atoms n, ca, c, cb as float4 (w=0)
__device__ float4 g_Rt4[N_RES * 3];     // 12 floats: R[0..8], t[0..2]
__device__ float  g_local[N_RES * 12];  // R^T (bb - t)
__device__ float2 g_meta[N_RES];        // (noised, int_as_float(seq))
__device__ int    g_mask_kind;          // 0=bool(u8), 1=int32, 2=float32

__constant__ float c_freq[8] = {
    1.0f, 0.31622776601683794f, 0.1f, 0.03162277660168379f,
    0.01f, 0.0031622776601683794f, 0.001f, 0.00031622776601683794f
};

#define RBF_DELTA 1.0666666666666667f    /* (4/3)*0.8 */
#define RBF_DSQ   1.1377777777777778f    /* delta^2 */
#define RBF_C     0.10274027f            /* exp(-2*delta^2) */

// ---------------- mask dtype detection (1 block, batched MLP-19 loads) ----------------
// Reads first 4864 words (= 19456 bytes, in-bounds under every interpretation
// of the 20000-element mask). int32 0/1 -> words all in {0,1}; float32 0/1 ->
// words all in {0, 0x3F800000}; packed bool bytes -> neither.
__global__ void detect_kernel(const unsigned int* __restrict__ mask_w) {
    __shared__ int s_not01, s_notf;
    if (threadIdx.x == 0) { s_not01 = 0; s_notf = 0; }
    __syncthreads();
    unsigned int v[19];
    #pragma unroll
    for (int k = 0; k < 19; k++) v[k] = mask_w[threadIdx.x + 256 * k];
    int not01 = 0, notf = 0;
    #pragma unroll
    for (int k = 0; k < 19; k++) {
        if (v[k] > 1u) not01 = 1;
        if (v[k] != 0u && v[k] != 0x3F800000u) notf = 1;
    }
    if (not01) atomicOr(&s_not01, 1);
    if (notf)  atomicOr(&s_notf, 1);
    __syncthreads();
    if (threadIdx.x == 0) {
        int kind;
        if (!s_notf)       kind = 2;   // float32
        else if (!s_not01) kind = 1;   // int32
        else               kind = 0;   // bool bytes
        g_mask_kind = kind;
    }
}

// ---------------- prep: residue geometry + packed metadata ----------------
__global__ void prep_kernel(const float* __restrict__ atom14,
                            const float* __restrict__ rig,
                            const int*   __restrict__ seq,
                            const void*  __restrict__ mask) {
    int r = blockIdx.x * blockDim.x + threadIdx.x;
    if (r >= N_RES) return;

    const float* a = atom14 + (size_t)r * 42;   // 14 atoms * 3
    float n0 = a[0], n1 = a[1], n2 = a[2];
    float ca0 = a[3], ca1 = a[4], ca2 = a[5];
    float c0 = a[6], c1 = a[7], c2 = a[8];

    float b0 = ca0 - n0, b1 = ca1 - n1, b2 = ca2 - n2;
    float e0 = c0 - ca0, e1 = c1 - ca1, e2 = c2 - ca2;
    float ax = b1 * e2 - b2 * e1;
    float ay = b2 * e0 - b0 * e2;
    float az = b0 * e1 - b1 * e0;
    float cb0 = -0.58273431f * ax + 0.56802827f * b0 - 0.54067466f * e0 + ca0;
    float cb1 = -0.58273431f * ay + 0.56802827f * b1 - 0.54067466f * e1 + ca1;
    float cb2 = -0.58273431f * az + 0.56802827f * b2 - 0.54067466f * e2 + ca2;

    float bb[12] = { n0, n1, n2, ca0, ca1, ca2, c0, c1, c2, cb0, cb1, cb2 };
    g_bb4[r * 4 + 0] = make_float4(n0, n1, n2, 0.f);
    g_bb4[r * 4 + 1] = make_float4(ca0, ca1, ca2, 0.f);
    g_bb4[r * 4 + 2] = make_float4(c0, c1, c2, 0.f);
    g_bb4[r * 4 + 3] = make_float4(cb0, cb1, cb2, 0.f);

    const float* q = rig + (size_t)r * 7;
    float qw = q[0], qx = q[1], qy = q[2], qz = q[3];
    float inv = rsqrtf(qw * qw + qx * qx + qy * qy + qz * qz);
    qw *= inv; qx *= inv; qy *= inv; qz *= inv;

    float R[9];
    R[0] = 1.f - 2.f * (qy * qy + qz * qz);
    R[1] = 2.f * (qx * qy - qw * qz);
    R[2] = 2.f * (qx * qz + qw * qy);
    R[3] = 2.f * (qx * qy + qw * qz);
    R[4] = 1.f - 2.f * (qx * qx + qz * qz);
    R[5] = 2.f * (qy * qz - qw * qx);
    R[6] = 2.f * (qx * qz - qw * qy);
    R[7] = 2.f * (qy * qz + qw * qx);
    R[8] = 1.f - 2.f * (qx * qx + qy * qy);
    float t0 = q[4], t1 = q[5], t2 = q[6];

    g_Rt4[r * 3 + 0] = make_float4(R[0], R[1], R[2], R[3]);
    g_Rt4[r * 3 + 1] = make_float4(R[4], R[5], R[6], R[7]);
    g_Rt4[r * 3 + 2] = make_float4(R[8], t0, t1, t2);

    // local[k][i] = sum_j R[j][i] * (bb[k][j] - t[j])
    #pragma unroll
    for (int k = 0; k < 4; k++) {
        float vx = bb[k * 3 + 0] - t0;
        float vy = bb[k * 3 + 1] - t1;
        float vz = bb[k * 3 + 2] - t2;
        #pragma unroll
        for (int i = 0; i < 3; i++) {
            g_local[r * 12 + k * 3 + i] = R[0 + i] * vx + R[3 + i] * vy + R[6 + i] * vz;
        }
    }

    int kind = g_mask_kind;
    float noised;
    if (kind == 0)      noised = ((const unsigned char*)mask)[r] ? 1.f : 0.f;
    else if (kind == 1) noised = ((const int*)mask)[r] ? 1.f : 0.f;
    else                noised = (((const float*)mask)[r] != 0.f) ? 1.f : 0.f;
    g_meta[r] = make_float2(noised, __int_as_float(seq[r]));
}

// ---------------- per-edge feature kernel: 1 warp / edge, direct-to-GMEM ----------------
__global__ __launch_bounds__(EPB * 32) void edge_kernel(
    const int* __restrict__ eidx,     // [2, N_EDGE]: row0=dst, row1=src
    float* __restrict__ out) {

    __shared__ float4 sstage4[EPB][7];

    int w    = threadIdx.x >> 5;
    int lane = threadIdx.x & 31;
    int e    = blockIdx.x * EPB + w;

    int dst = eidx[e];
    int src = eidx[N_EDGE + e];

    // register gathers (broadcast-heavy, L2-resident tables)
    float4 f4s = g_bb4[src * 4 + ((lane >> 2) & 3)];   // src atom i  (lanes 0-15 meaningful)
    float4 f4d = g_bb4[dst * 4 + (lane & 3)];          // dst atom j
    int c = min(max(lane - 4, 0), 2);
    float4 f4rt = g_Rt4[src * 3 + c];                  // R/t chunk (lanes 4-6 meaningful)
    float2 ms = g_meta[src];
    float2 md = g_meta[dst];

    // stage: floats [0..15] = bb_dst atoms (xyzw), [16..24] = R, [25..27] = t
    float* st = (float*)sstage4[w];
    if (lane < 4)               sstage4[w][lane] = f4d;
    if (lane >= 4 && lane < 7)  sstage4[w][lane] = f4rt;
    __syncwarp();

    float noised_src = ms.x, noised_dst = md.x;
    float keep_src = 1.f - noised_src;
    float keep_dst = 1.f - noised_dst;
    int hot_src = __float_as_int(ms.y) + 2;    // one-hot position within row, [2,22]
    int hot_dst = __float_as_int(md.y) + 23;   // one-hot position within row, [23,43]

    float* __restrict__ row = out + (size_t)e * FEAT;

    // ---- region A: [0..43] flags + one-hots, 11 lanes x STG.128 ----
    if (lane < 11) {
        float4 v4;
        float* vp = &v4.x;
        #pragma unroll
        for (int cc = 0; cc < 4; cc++) {
            int idx = 4 * lane + cc;
            float x = (idx == hot_src) ? keep_src : 0.f;
            x = (idx == hot_dst) ? keep_dst : x;
            vp[cc] = x;
        }
        if (lane == 0) { v4.x = noised_dst; v4.y = noised_src; }
        __stcs((float4*)(row + 4 * lane), v4);
    }

    // ---- region B: [44..299] RBF of 16 dists, 16 bins each ----
    // lanes 0-15 hold src atom (lane>>2) and dst atom (lane&3) in registers:
    // each computes its distance; two dense STG.128 sweeps cover [44..171] and
    // [172..299]. Bins via geometric recurrence: 2 MUFU + 6 FMUL per sweep.
    float dx = f4s.x - f4d.x + EPSV;
    float dy = f4s.y - f4d.y + EPSV;
    float dz = f4s.z - f4d.z + EPSV;
    float D = sqrtf(dx * dx + dy * dy + dz * dz);

    float mu0 = 2.0f + (float)(4 * (lane & 3)) * (20.0f / 15.0f);
    {
        // sweep 1: lane L -> floats [44+4L..47+4L], pair = L>>2, bins 4*(L&3)..+3
        float Da = __shfl_sync(0xFFFFFFFFu, D, lane >> 2);
        float z0 = (Da - mu0) * 0.8f;
        float r0 = __expf(-z0 * z0);
        float g  = __expf(fminf(2.0f * RBF_DELTA * z0 - RBF_DSQ, 80.f));
        float r1 = r0 * g; g *= RBF_C;
        float r2 = r1 * g; g *= RBF_C;
        float r3 = r2 * g;
        __stcs((float4*)(row + 44 + 4 * lane), make_float4(r0, r1, r2, r3));

        // sweep 2: lane L -> floats [172+4L..175+4L], pair = 8 + (L>>2)
        float Db = __shfl_sync(0xFFFFFFFFu, D, 8 + (lane >> 2));
        z0 = (Db - mu0) * 0.8f;
        r0 = __expf(-z0 * z0);
        g  = __expf(fminf(2.0f * RBF_DELTA * z0 - RBF_DSQ, 80.f));
        r1 = r0 * g; g *= RBF_C;
        r2 = r1 * g; g *= RBF_C;
        r3 = r2 * g;
        __stcs((float4*)(row + 172 + 4 * lane), make_float4(r0, r1, r2, r3));
    }

    // ---- region C: [300..315] positional enc (fast sin/cos, HW range red.) ----
    if (lane < 16) {
        float dp = (float)(dst - src);
        float ang = dp * c_freq[lane & 7];
        __stcs(row + 300 + lane, (lane < 8) ? __cosf(ang) : __sinf(ang));
    }

    // ---- regions D+E fused: [316..339] one predicated STG over 24 lanes ----
    // lanes 0..11:  src local frame (direct L2 gather) * keep_src
    // lanes 12..23: dst backbone in src frame * keep_dst
    if (lane < 24) {
        float v;
        if (lane < 12) {
            v = g_local[src * 12 + lane] * keep_src;
        } else {
            int l = lane - 12;
            int kk = l / 3, ii = l - kk * 3;
            float acc = 0.f;
            #pragma unroll
            for (int jj = 0; jj < 3; jj++)
                acc += st[16 + jj * 3 + ii] * (st[kk * 4 + jj] - st[25 + jj]);
            v = acc * keep_dst;
        }
        __stcs(row + 316 + lane, v);
    }
}

// ---------------- launch ----------------
extern "C" void kernel_launch(void* const* d_in, const int* in_sizes, int n_in,
                              void* d_out, int out_size) {
    const float* atom14 = (const float*)d_in[0];
    const float* rigids = (const float*)d_in[1];
    const int*   seq    = (const int*)d_in[2];
    const void*  mask   = d_in[3];
    const int*   eidx   = (const int*)d_in[4];
    float* out = (float*)d_out;

    detect_kernel<<<1, 256>>>((const unsigned int*)mask);
    prep_kernel<<<(N_RES + 255) / 256, 256>>>(atom14, rigids, seq, mask);
    edge_kernel<<<N_EDGE / EPB, EPB * 32>>>(eidx, out);
}